// round 12
// baseline (speedup 1.0000x reference)
#include <cuda_runtime.h>
#include <cuda_fp16.h>

#define H 512
#define W 512
#define NP 24                 // 8*3 planes
#define WXROWS 502
#define WXCOLS 503
#define WYROWS 503
#define WYCOLS 502
#define NBANDS 12
#define BAND 43               // 12*43 = 516 >= 512
#define NBLK (NBANDS*NP)      // 288

__device__ float        g_part[NBLK * 3];   // per-block partials: gx, gy, norm
__device__ unsigned int g_count = 0;        // finished-block counter (self-resetting)

__device__ __forceinline__ float warp_red(float v) {
    #pragma unroll
    for (int o = 16; o; o >>= 1) v += __shfl_down_sync(0xffffffffu, v, o);
    return v;
}

__device__ __forceinline__ unsigned int h2u(__half2 h) {
    return *(const unsigned int*)&h;
}
__device__ __forceinline__ __half2 u2h(unsigned int u) {
    return *(const __half2*)&u;
}

struct Smem {
    __half2 ringX[10 * 512];   // 20480 B
    __half2 ringY[10 * 512];   // 20480 B
    uint4   Vpack[2][512];     // 16384 B (x=Vxa, y=Vya, z=Vxb, w=Vyb), parity ring
    __half2 Ybuf[8][512];      // 16384 B (Y window rows, ring by row&7)
    float   edge[4][16][3];    //   768 B (warp-boundary row values, ring by row&3)
    float   red[96];           //   384 B
    int     is_last;
};
#define SMEM_BYTES ((int)sizeof(Smem))

__global__ void __launch_bounds__(512, 2) win_kernel(
        const float* __restrict__ Al,
        const float* __restrict__ Ar,
        const float* __restrict__ Ai,
        float* __restrict__ out) {
    extern __shared__ unsigned char smraw[];
    Smem* sm = (Smem*)smraw;

    const int c    = threadIdx.x;
    const int lane = c & 31, w = c >> 5;
    const int p    = blockIdx.y;
    const int R0   = blockIdx.x * BAND;
    const int R1   = min(R0 + BAND, H);
    const int rend = min(R1 + 9, H - 1);

    // hoisted guard bounds
    const int RxLim = min(R1, WXROWS);       // rx valid: R0 <= rx < RxLim
    const int RyLim = min(R1, WYROWS - 1);   // ry valid: R0 <= ry <= RyLim
    const bool cWX = (c < WXCOLS);
    const bool cWY = (c < WYCOLS);

    const __half2 hz = __floats2half2_rn(0.f, 0.f);
    #pragma unroll
    for (int k = c; k < 10 * 512; k += 512) { sm->ringX[k] = hz; sm->ringY[k] = hz; }

    const size_t pb = (size_t)p * H * W;
    const float* Bl = Al + pb;
    const float* Br = Ar + pb;
    const float* Bi = Ai + pb;

    // 4-deep register pipeline: rows r, r+1 (cur), r+2, r+3 (nxt)
    float c0l = Bl[R0 * W + c],       c0r = Br[R0 * W + c],       c0i = Bi[R0 * W + c];
    float c1l = Bl[(R0 + 1) * W + c], c1r = Br[(R0 + 1) * W + c], c1i = Bi[(R0 + 1) * W + c];
    float n0l = Bl[(R0 + 2) * W + c], n0r = Br[(R0 + 2) * W + c], n0i = Bi[(R0 + 2) * W + c];
    float n1l = Bl[(R0 + 3) * W + c], n1r = Br[(R0 + 3) * W + c], n1i = Bi[(R0 + 3) * W + c];
    float pl = 0.f, pr = 0.f, pv = 0.f;
    if (lane == 0) {
        sm->edge[R0 & 3][w][0] = c0l;       sm->edge[R0 & 3][w][1] = c0r;       sm->edge[R0 & 3][w][2] = c0i;
        sm->edge[(R0 + 1) & 3][w][0] = c1l; sm->edge[(R0 + 1) & 3][w][1] = c1r; sm->edge[(R0 + 1) & 3][w][2] = c1i;
    }

    __half2 Vx = hz, Vy = hz;
    __half2 pend0 = hz, pend1 = hz;   // pending X box values (rows r-12, r-11 at base r)
    float gxacc = 0.f, gyacc = 0.f, normacc = 0.f;
    int sX = 0, sY = 0;               // ring slot offsets (units of __half2 index)
    __syncthreads();

    for (int r = R0; r <= rend; r += 2) {
        const bool hasB = (r + 1 <= rend);
        const int  sp   = ((r - R0) >> 1) & 1;

        // prefetch rows r+4, r+5 (consumed next superiteration)
        float nn0l, nn0r, nn0i, nn1l, nn1r, nn1i;
        {
            int ra4 = min(r + 4, rend), ra5 = min(r + 5, rend);
            nn0l = Bl[ra4 * W + c]; nn0r = Br[ra4 * W + c]; nn0i = Bi[ra4 * W + c];
            nn1l = Bl[ra5 * W + c]; nn1r = Br[ra5 * W + c]; nn1i = Bi[ra5 * W + c];
        }
        // publish edges for rows r+2, r+3 (read next superiteration)
        if (lane == 0) {
            sm->edge[(r + 2) & 3][w][0] = n0l; sm->edge[(r + 2) & 3][w][1] = n0r; sm->edge[(r + 2) & 3][w][2] = n0i;
            sm->edge[(r + 3) & 3][w][0] = n1l; sm->edge[(r + 3) & 3][w][1] = n1r; sm->edge[(r + 3) & 3][w][2] = n1i;
        }

        unsigned int Vxa_bits, Vya_bits;
        // ================= phase 1, row ra = r =================
        {
            float rl = __shfl_down_sync(0xffffffffu, c0l, 1);
            float rr = __shfl_down_sync(0xffffffffu, c0r, 1);
            float rv = __shfl_down_sync(0xffffffffu, c0i, 1);
            float uy = 0.f, dy = 0.f;
            if (c < W - 1) {
                if (lane == 31) {
                    rl = sm->edge[r & 3][w + 1][0];
                    rr = sm->edge[r & 3][w + 1][1];
                    rv = sm->edge[r & 3][w + 1][2];
                }
                float gl = rl - c0l, gr = rr - c0r, gi = rv - c0i;
                uy = fabsf(gl) + fabsf(gr);
                dy = fabsf(gi);
                if (r < R1) gyacc += fabsf(gl + gr - gi);
            }
            {
                __half2 h = __floats2half2_rn(uy, dy);
                __half2 old = sm->ringY[sY + c];
                sm->ringY[sY + c] = h;
                Vy = __hadd2(Vy, __hsub2(h, old));
                sY = (sY == 4608) ? 0 : sY + 512;
            }
            if (r > R0) {   // gx row r-1 from (c0 - prev)
                float gl = c0l - pl, gr = c0r - pr, gi = c0i - pv;
                if (r - 1 < R1) gxacc += fabsf(gl + gr - gi);
                __half2 h = __floats2half2_rn(fabsf(gl) + fabsf(gr), fabsf(gi));
                __half2 old = sm->ringX[sX + c];
                sm->ringX[sX + c] = h;
                Vx = __hadd2(Vx, __hsub2(h, old));
                sX = (sX == 4608) ? 0 : sX + 512;
            }
            Vxa_bits = h2u(Vx);
            Vya_bits = h2u(Vy);
        }
        // ================= phase 1, row rb = r+1 =================
        if (hasB) {
            float rl = __shfl_down_sync(0xffffffffu, c1l, 1);
            float rr = __shfl_down_sync(0xffffffffu, c1r, 1);
            float rv = __shfl_down_sync(0xffffffffu, c1i, 1);
            float uy = 0.f, dy = 0.f;
            if (c < W - 1) {
                if (lane == 31) {
                    rl = sm->edge[(r + 1) & 3][w + 1][0];
                    rr = sm->edge[(r + 1) & 3][w + 1][1];
                    rv = sm->edge[(r + 1) & 3][w + 1][2];
                }
                float gl = rl - c1l, gr = rr - c1r, gi = rv - c1i;
                uy = fabsf(gl) + fabsf(gr);
                dy = fabsf(gi);
                if (r + 1 < R1) gyacc += fabsf(gl + gr - gi);
            }
            {
                __half2 h = __floats2half2_rn(uy, dy);
                __half2 old = sm->ringY[sY + c];
                sm->ringY[sY + c] = h;
                Vy = __hadd2(Vy, __hsub2(h, old));
                sY = (sY == 4608) ? 0 : sY + 512;
            }
            {   // gx row r from (c1 - c0)
                float gl = c1l - c0l, gr = c1r - c0r, gi = c1i - c0i;
                if (r < R1) gxacc += fabsf(gl + gr - gi);
                __half2 h = __floats2half2_rn(fabsf(gl) + fabsf(gr), fabsf(gi));
                __half2 old = sm->ringX[sX + c];
                sm->ringX[sX + c] = h;
                Vx = __hadd2(Vx, __hsub2(h, old));
                sX = (sX == 4608) ? 0 : sX + 512;
            }
        }
        // single packed publish: both rows' V in one STS.128
        sm->Vpack[sp][c] = make_uint4(Vxa_bits, Vya_bits, h2u(Vx), h2u(Vy));

        __syncthreads();   // single barrier per 2 rows

        // ======= phase 2: ratios for pendings (X rows r-12, r-11) =======
        {
            const int rxp = r - 12;
            if (rxp >= R0 && rxp < RxLim && cWX) {
                int t = rxp + c;
                int ry = rxp, cy = t;
                if (t >= WYCOLS) { ry = rxp + 1; cy = t - WYCOLS; }
                float2 yv = __half22float2(sm->Ybuf[ry & 7][cy]);
                float2 xv = __half22float2(pend0);
                normacc += __fdividef(xv.x + yv.x, xv.y + yv.y + 1e-4f);
            }
        }
        {
            const int rxp = r - 11;
            if (rxp >= R0 && rxp < RxLim && cWX) {
                int t = rxp + c;
                int ry = rxp, cy = t;
                if (t >= WYCOLS) { ry = rxp + 1; cy = t - WYCOLS; }
                float2 yv = __half22float2(sm->Ybuf[ry & 7][cy]);
                float2 xv = __half22float2(pend1);
                normacc += __fdividef(xv.x + yv.x, xv.y + yv.y + 1e-4f);
            }
        }
        // ======= phase 2: fused box sums for both rows (10 x LDS.128) =======
        if (cWX) {
            __half2 sxa = hz, sya = hz, sxb = hz, syb = hz;
            #pragma unroll
            for (int d = 0; d < 10; ++d) {
                uint4 u = sm->Vpack[sp][c + d];
                sxa = __hadd2(sxa, u2h(u.x));
                sya = __hadd2(sya, u2h(u.y));
                sxb = __hadd2(sxb, u2h(u.z));
                syb = __hadd2(syb, u2h(u.w));
            }
            // row a outputs: ry = r-9, rx = r-10
            {
                const int ry = r - 9, rx = r - 10;
                if (ry >= R0 && ry <= RyLim && cWY) sm->Ybuf[ry & 7][c] = sya;
                if (rx >= R0 && rx < RxLim)         pend0 = sxa;
            }
            // row b outputs: ry = r-8, rx = r-9
            {
                const int ry = r - 8, rx = r - 9;
                if (ry >= R0 && ry <= RyLim && cWY) sm->Ybuf[ry & 7][c] = syb;
                if (rx >= R0 && rx < RxLim)         pend1 = sxb;
            }
        }

        // rotate pipeline by 2 rows
        pl = c1l; pr = c1r; pv = c1i;
        c0l = n0l; c0r = n0r; c0i = n0i;
        c1l = n1l; c1r = n1r; c1i = n1i;
        n0l = nn0l; n0r = nn0r; n0i = nn0i;
        n1l = nn1l; n1r = nn1r; n1i = nn1i;
    }

    // ---- epilogue: pendings from the last superiteration ----
    __syncthreads();
    {
        const int rl = rend - ((rend - R0) & 1);   // last loop base
        #pragma unroll
        for (int q = 0; q < 2; ++q) {
            const int rxp = (q == 0) ? (rl - 10) : (rl - 9);
            __half2 pend = (q == 0) ? pend0 : pend1;
            if (rxp >= R0 && rxp < RxLim && cWX) {
                int t = rxp + c;
                int ry = rxp, cy = t;
                if (t >= WYCOLS) { ry = rxp + 1; cy = t - WYCOLS; }
                float2 yv = __half22float2(sm->Ybuf[ry & 7][cy]);
                float2 xv = __half22float2(pend);
                normacc += __fdividef(xv.x + yv.x, xv.y + yv.y + 1e-4f);
            }
        }
    }

    // ---- block reduce: gx, gy, norm -> per-block partials ----
    __syncthreads();
    float vx = warp_red(gxacc);
    float vy = warp_red(gyacc);
    float vn = warp_red(normacc);
    if (lane == 0) { sm->red[w] = vx; sm->red[32 + w] = vy; sm->red[64 + w] = vn; }
    __syncthreads();
    if (w == 0) {
        float a = (lane < 16) ? sm->red[lane]      : 0.f;
        float b = (lane < 16) ? sm->red[32 + lane] : 0.f;
        float n = (lane < 16) ? sm->red[64 + lane] : 0.f;
        a = warp_red(a);
        b = warp_red(b);
        n = warp_red(n);
        if (lane == 0) {
            int bid = blockIdx.y * NBANDS + blockIdx.x;
            g_part[bid * 3 + 0] = a;
            g_part[bid * 3 + 1] = b;
            g_part[bid * 3 + 2] = n;
            __threadfence();
            unsigned int old = atomicAdd(&g_count, 1u);
            sm->is_last = (old == NBLK - 1) ? 1 : 0;
        }
    }
    __syncthreads();

    // ---- last block finishes the reduction ----
    if (sm->is_last && w == 0) {
        __threadfence();
        double a = 0.0, b = 0.0, n = 0.0;
        for (int i = lane; i < NBLK; i += 32) {
            a += (double)g_part[i * 3 + 0];
            b += (double)g_part[i * 3 + 1];
            n += (double)g_part[i * 3 + 2];
        }
        #pragma unroll
        for (int o = 16; o; o >>= 1) {
            a += __shfl_down_sync(0xffffffffu, a, o);
            b += __shfl_down_sync(0xffffffffu, b, o);
            n += __shfl_down_sync(0xffffffffu, n, o);
        }
        if (lane == 0) {
            double norm_loss = n / 6060144.0;                 // 24 * 252506
            double grad_loss = a / 6279168.0 + b / 6279168.0; // 24 * 511 * 512
            out[0] = (float)(norm_loss * 1e-4 + grad_loss);
            g_count = 0;   // reset for next graph replay
        }
    }
}

extern "C" void kernel_launch(void* const* d_in, const int* in_sizes, int n_in,
                              void* d_out, int out_size) {
    const float* l  = (const float*)d_in[0];
    const float* r  = (const float*)d_in[1];
    const float* ii = (const float*)d_in[2];
    float* out = (float*)d_out;

    cudaFuncSetAttribute(win_kernel,
                         cudaFuncAttributeMaxDynamicSharedMemorySize, SMEM_BYTES);

    dim3 g1(NBANDS, NP);
    win_kernel<<<g1, 512, SMEM_BYTES>>>(l, r, ii, out);
}

// round 13
// speedup vs baseline: 1.1375x; 1.1375x over previous
#include <cuda_runtime.h>
#include <cuda_fp16.h>

#define H 512
#define W 512
#define NP 24                 // 8*3 planes
#define WXROWS 502
#define WXCOLS 503
#define WYROWS 503
#define WYCOLS 502
#define NBANDS 12
#define BAND 43               // 12*43 = 516 >= 512
#define NBLK (NBANDS*NP)      // 288

__device__ float        g_part[NBLK * 3];   // per-block partials: gx, gy, norm
__device__ unsigned int g_count = 0;        // finished-block counter (self-resetting)

__device__ __forceinline__ float warp_red(float v) {
    #pragma unroll
    for (int o = 16; o; o >>= 1) v += __shfl_down_sync(0xffffffffu, v, o);
    return v;
}

__device__ __forceinline__ unsigned int h2u(__half2 h) {
    return *(const unsigned int*)&h;
}
__device__ __forceinline__ __half2 u2h(unsigned int u) {
    return *(const __half2*)&u;
}

struct Smem {
    __half2 ringX[10 * 512];   // 20480 B
    __half2 ringY[10 * 512];   // 20480 B
    uint2   Vpack[4][512];     // 16384 B (.x=half2(Vxn,Vxd), .y=half2(Vyn,Vyd)), ring of 4
    __half2 Ybuf[8][512];      // 16384 B (Y window rows, ring by row&7)
    float   red[96];           //   384 B
    int     is_last;
};
#define SMEM_BYTES ((int)sizeof(Smem))

__global__ void __launch_bounds__(512, 2) win_kernel(
        const float* __restrict__ Al,
        const float* __restrict__ Ar,
        const float* __restrict__ Ai,
        float* __restrict__ out) {
    extern __shared__ unsigned char smraw[];
    Smem* sm = (Smem*)smraw;

    const int c    = threadIdx.x;
    const int lane = c & 31, w = c >> 5;
    const int p    = blockIdx.y;
    const int R0   = blockIdx.x * BAND;
    const int R1   = min(R0 + BAND, H);
    const int rend = min(R1 + 9, H - 1);

    // hoisted guard bounds
    const int RxLim = min(R1, WXROWS);       // rx valid: R0 <= rx < RxLim
    const int RyLim = min(R1, WYROWS - 1);   // ry valid: R0 <= ry <= RyLim
    const bool cWX = (c < WXCOLS);
    const bool cWY = (c < WYCOLS);
    const bool cG  = (c < W - 1);
    const int  cn  = min(c + 1, W - 1);      // shifted column (clamped; value unused at c=511)

    const __half2 hz = __floats2half2_rn(0.f, 0.f);
    #pragma unroll
    for (int k = c; k < 10 * 512; k += 512) { sm->ringX[k] = hz; sm->ringY[k] = hz; }

    const size_t pb = (size_t)p * H * W;
    const float* Bl = Al + pb;
    const float* Br = Ar + pb;
    const float* Bi = Ai + pb;
    const float* Sl = Bl + cn;   // shifted bases (row offset added per use)
    const float* Sr = Br + cn;
    const float* Si = Bi + cn;

    // 4-deep register pipeline: rows r, r+1 (cur), r+2, r+3 (nxt)
    float c0l = Bl[R0 * W + c],       c0r = Br[R0 * W + c],       c0i = Bi[R0 * W + c];
    float c1l = Bl[(R0 + 1) * W + c], c1r = Br[(R0 + 1) * W + c], c1i = Bi[(R0 + 1) * W + c];
    float n0l = Bl[(R0 + 2) * W + c], n0r = Br[(R0 + 2) * W + c], n0i = Bi[(R0 + 2) * W + c];
    float n1l = Bl[(R0 + 3) * W + c], n1r = Br[(R0 + 3) * W + c], n1i = Bi[(R0 + 3) * W + c];
    float pl = 0.f, pr = 0.f, pv = 0.f;

    __half2 Vx = hz, Vy = hz;
    __half2 pend0 = hz, pend1 = hz;   // pending X box values (rows r-12, r-11 at base r)
    float gxacc = 0.f, gyacc = 0.f, normacc = 0.f;
    int sX = 0, sY = 0;               // ring slot offsets (units of __half2 index)
    __syncthreads();

    #pragma unroll 2
    for (int r = R0; r <= rend; r += 2) {
        const bool hasB = (r + 1 <= rend);
        const int  vp   = (((r - R0) >> 1) & 1) * 2;

        // shifted (c+1) values for gy — L1 hits (lines loaded by prefetch 2 supers ago)
        float s0l = Sl[r * W], s0r = Sr[r * W], s0i = Si[r * W];
        float s1l = 0.f, s1r = 0.f, s1i = 0.f;
        if (hasB) { s1l = Sl[(r + 1) * W]; s1r = Sr[(r + 1) * W]; s1i = Si[(r + 1) * W]; }

        // prefetch rows r+4, r+5 (consumed next superiteration)
        float nn0l, nn0r, nn0i, nn1l, nn1r, nn1i;
        {
            int ra4 = min(r + 4, rend), ra5 = min(r + 5, rend);
            nn0l = Bl[ra4 * W + c]; nn0r = Br[ra4 * W + c]; nn0i = Bi[ra4 * W + c];
            nn1l = Bl[ra5 * W + c]; nn1r = Br[ra5 * W + c]; nn1i = Bi[ra5 * W + c];
        }

        // ================= phase 1, row ra = r =================
        {
            // gx row r-1 from (c0 - prev)   [registers only]
            if (r > R0) {
                float gl = c0l - pl, gr = c0r - pr, gi = c0i - pv;
                if (r - 1 < R1) gxacc += fabsf(gl + gr - gi);
                __half2 h = __floats2half2_rn(fabsf(gl) + fabsf(gr), fabsf(gi));
                __half2 old = sm->ringX[sX + c];
                sm->ringX[sX + c] = h;
                Vx = __hadd2(Vx, __hsub2(h, old));
                sX = (sX == 4608) ? 0 : sX + 512;
            }
            // gy row r from shifted global values
            float uy = 0.f, dy = 0.f;
            if (cG) {
                float gl = s0l - c0l, gr = s0r - c0r, gi = s0i - c0i;
                uy = fabsf(gl) + fabsf(gr);
                dy = fabsf(gi);
                if (r < R1) gyacc += fabsf(gl + gr - gi);
            }
            {
                __half2 h = __floats2half2_rn(uy, dy);
                __half2 old = sm->ringY[sY + c];
                sm->ringY[sY + c] = h;
                Vy = __hadd2(Vy, __hsub2(h, old));
                sY = (sY == 4608) ? 0 : sY + 512;
            }
            uint2 u;
            u.x = h2u(Vx);
            u.y = h2u(Vy);
            sm->Vpack[vp][c] = u;
        }
        // ================= phase 1, row rb = r+1 =================
        if (hasB) {
            {   // gx row r from (c1 - c0)
                float gl = c1l - c0l, gr = c1r - c0r, gi = c1i - c0i;
                if (r < R1) gxacc += fabsf(gl + gr - gi);
                __half2 h = __floats2half2_rn(fabsf(gl) + fabsf(gr), fabsf(gi));
                __half2 old = sm->ringX[sX + c];
                sm->ringX[sX + c] = h;
                Vx = __hadd2(Vx, __hsub2(h, old));
                sX = (sX == 4608) ? 0 : sX + 512;
            }
            float uy = 0.f, dy = 0.f;
            if (cG) {
                float gl = s1l - c1l, gr = s1r - c1r, gi = s1i - c1i;
                uy = fabsf(gl) + fabsf(gr);
                dy = fabsf(gi);
                if (r + 1 < R1) gyacc += fabsf(gl + gr - gi);
            }
            {
                __half2 h = __floats2half2_rn(uy, dy);
                __half2 old = sm->ringY[sY + c];
                sm->ringY[sY + c] = h;
                Vy = __hadd2(Vy, __hsub2(h, old));
                sY = (sY == 4608) ? 0 : sY + 512;
            }
            uint2 u;
            u.x = h2u(Vx);
            u.y = h2u(Vy);
            sm->Vpack[vp + 1][c] = u;
        }

        __syncthreads();   // single barrier per 2 rows

        // ======= phase 2: ratios for pendings (X rows r-12, r-11) =======
        {
            const int rxp = r - 12;
            if (rxp >= R0 && rxp < RxLim && cWX) {
                int t = rxp + c;
                int ry = rxp, cy = t;
                if (t >= WYCOLS) { ry = rxp + 1; cy = t - WYCOLS; }
                float2 yv = __half22float2(sm->Ybuf[ry & 7][cy]);
                float2 xv = __half22float2(pend0);
                normacc += __fdividef(xv.x + yv.x, xv.y + yv.y + 1e-4f);
            }
        }
        {
            const int rxp = r - 11;
            if (rxp >= R0 && rxp < RxLim && cWX) {
                int t = rxp + c;
                int ry = rxp, cy = t;
                if (t >= WYCOLS) { ry = rxp + 1; cy = t - WYCOLS; }
                float2 yv = __half22float2(sm->Ybuf[ry & 7][cy]);
                float2 xv = __half22float2(pend1);
                normacc += __fdividef(xv.x + yv.x, xv.y + yv.y + 1e-4f);
            }
        }
        // ======= phase 2: boxes, row ra = r =======
        {
            const int ry = r - 9, rx = r - 10;
            const bool doY = (ry >= R0 && ry <= RyLim && cWY);
            const bool doX = (rx >= R0 && rx < RxLim && cWX);
            if (doY || doX) {
                __half2 sx = hz, sy = hz;
                #pragma unroll
                for (int d = 0; d < 10; ++d) {
                    uint2 u = sm->Vpack[vp][c + d];
                    sx = __hadd2(sx, u2h(u.x));
                    sy = __hadd2(sy, u2h(u.y));
                }
                if (doY) sm->Ybuf[ry & 7][c] = sy;
                if (doX) pend0 = sx;
            }
        }
        // ======= phase 2: boxes, row rb = r+1 =======
        if (hasB) {
            const int ry = r - 8, rx = r - 9;
            const bool doY = (ry >= R0 && ry <= RyLim && cWY);
            const bool doX = (rx >= R0 && rx < RxLim && cWX);
            if (doY || doX) {
                __half2 sx = hz, sy = hz;
                #pragma unroll
                for (int d = 0; d < 10; ++d) {
                    uint2 u = sm->Vpack[vp + 1][c + d];
                    sx = __hadd2(sx, u2h(u.x));
                    sy = __hadd2(sy, u2h(u.y));
                }
                if (doY) sm->Ybuf[ry & 7][c] = sy;
                if (doX) pend1 = sx;
            }
        }

        // rotate pipeline by 2 rows
        pl = c1l; pr = c1r; pv = c1i;
        c0l = n0l; c0r = n0r; c0i = n0i;
        c1l = n1l; c1r = n1r; c1i = n1i;
        n0l = nn0l; n0r = nn0r; n0i = nn0i;
        n1l = nn1l; n1r = nn1r; n1i = nn1i;
    }

    // ---- epilogue: pendings from the last superiteration ----
    __syncthreads();
    {
        const int rl = rend - ((rend - R0) & 1);   // last loop base
        #pragma unroll
        for (int q = 0; q < 2; ++q) {
            const int rxp = (q == 0) ? (rl - 10) : (rl - 9);
            __half2 pend = (q == 0) ? pend0 : pend1;
            if (rxp >= R0 && rxp < RxLim && cWX) {
                int t = rxp + c;
                int ry = rxp, cy = t;
                if (t >= WYCOLS) { ry = rxp + 1; cy = t - WYCOLS; }
                float2 yv = __half22float2(sm->Ybuf[ry & 7][cy]);
                float2 xv = __half22float2(pend);
                normacc += __fdividef(xv.x + yv.x, xv.y + yv.y + 1e-4f);
            }
        }
    }

    // ---- block reduce: gx, gy, norm -> per-block partials ----
    __syncthreads();
    float vx = warp_red(gxacc);
    float vy = warp_red(gyacc);
    float vn = warp_red(normacc);
    if (lane == 0) { sm->red[w] = vx; sm->red[32 + w] = vy; sm->red[64 + w] = vn; }
    __syncthreads();
    if (w == 0) {
        float a = (lane < 16) ? sm->red[lane]      : 0.f;
        float b = (lane < 16) ? sm->red[32 + lane] : 0.f;
        float n = (lane < 16) ? sm->red[64 + lane] : 0.f;
        a = warp_red(a);
        b = warp_red(b);
        n = warp_red(n);
        if (lane == 0) {
            int bid = blockIdx.y * NBANDS + blockIdx.x;
            g_part[bid * 3 + 0] = a;
            g_part[bid * 3 + 1] = b;
            g_part[bid * 3 + 2] = n;
            __threadfence();
            unsigned int old = atomicAdd(&g_count, 1u);
            sm->is_last = (old == NBLK - 1) ? 1 : 0;
        }
    }
    __syncthreads();

    // ---- last block finishes the reduction ----
    if (sm->is_last && w == 0) {
        __threadfence();
        double a = 0.0, b = 0.0, n = 0.0;
        for (int i = lane; i < NBLK; i += 32) {
            a += (double)g_part[i * 3 + 0];
            b += (double)g_part[i * 3 + 1];
            n += (double)g_part[i * 3 + 2];
        }
        #pragma unroll
        for (int o = 16; o; o >>= 1) {
            a += __shfl_down_sync(0xffffffffu, a, o);
            b += __shfl_down_sync(0xffffffffu, b, o);
            n += __shfl_down_sync(0xffffffffu, n, o);
        }
        if (lane == 0) {
            double norm_loss = n / 6060144.0;                 // 24 * 252506
            double grad_loss = a / 6279168.0 + b / 6279168.0; // 24 * 511 * 512
            out[0] = (float)(norm_loss * 1e-4 + grad_loss);
            g_count = 0;   // reset for next graph replay
        }
    }
}

extern "C" void kernel_launch(void* const* d_in, const int* in_sizes, int n_in,
                              void* d_out, int out_size) {
    const float* l  = (const float*)d_in[0];
    const float* r  = (const float*)d_in[1];
    const float* ii = (const float*)d_in[2];
    float* out = (float*)d_out;

    cudaFuncSetAttribute(win_kernel,
                         cudaFuncAttributeMaxDynamicSharedMemorySize, SMEM_BYTES);

    dim3 g1(NBANDS, NP);
    win_kernel<<<g1, 512, SMEM_BYTES>>>(l, r, ii, out);
}